// round 9
// baseline (speedup 1.0000x reference)
#include <cuda_runtime.h>
#include <math.h>

#define BB 4
#define CC 64
#define HH 64
#define WW 64
#define LLEN 4096
#define RR 64
#define DD 128
#define KK 4
#define NN 16
#define NCHA 128              // phase-A sub-chunks per (b,k), 32 steps each
#define CHL 64                // scanC chunk length (2 sub-chunks)
#define EPSV 1e-5f
#define BKLD (BB*LLEN*DD)
// smem: xsT [64][132] + xdbl[36][68] + Btr[64][24]
#define XDBL_SMEM (64*132 + 36*68 + 64*24)

typedef unsigned long long u64;
typedef unsigned int u32;

__device__ __forceinline__ u64 pk2(float lo, float hi) {
    u64 r; u32 a = __float_as_uint(lo), b = __float_as_uint(hi);
    asm("mov.b64 %0, {%1, %2};" : "=l"(r) : "r"(a), "r"(b));
    return r;
}
__device__ __forceinline__ u64 fma2(u64 a, u64 b, u64 c) {
    u64 d; asm("fma.rn.f32x2 %0, %1, %2, %3;" : "=l"(d) : "l"(a), "l"(b), "l"(c));
    return d;
}
__device__ __forceinline__ u64 mul2(u64 a, u64 b) {
    u64 d; asm("mul.rn.f32x2 %0, %1, %2;" : "=l"(d) : "l"(a), "l"(b));
    return d;
}
__device__ __forceinline__ void upk2(u64 v, float& lo, float& hi) {
    u32 a, b; asm("mov.b64 {%0, %1}, %2;" : "=r"(a), "=r"(b) : "l"(v));
    lo = __uint_as_float(a); hi = __uint_as_float(b);
}
// p2[j] = {r^(2j+1), r^(2j+2)}, dependency depth ~4
__device__ __forceinline__ void pow_tree2(float r, u64* p2) {
    float r2 = r*r, r4 = r2*r2, r8 = r4*r4;
    u64 q0 = pk2(r, r2), s2 = pk2(r2, r2), s4 = pk2(r4, r4), s8 = pk2(r8, r8);
    p2[0] = q0;
    p2[1] = mul2(q0, s2);
    p2[2] = mul2(q0, s4);
    p2[3] = mul2(p2[1], s4);
    p2[4] = mul2(q0, s8);
    p2[5] = mul2(p2[1], s8);
    p2[6] = mul2(p2[2], s8);
    p2[7] = mul2(p2[3], s8);
}
// fast softplus: branch-light, MUFU-based
__device__ __forceinline__ float softplus_f(float s) {
    float as = fabsf(s);
    float sp = fmaxf(s, 0.f) + __logf(1.f + __expf(-as));
    return (s > 20.f) ? s : sp;
}

// ---------------- scratch ----------------
__device__ float g_gamma[BB*CC];
__device__ float g_beta[BB*CC];
__device__ float g_cond[BB*DD];
__device__ float g_att[BB*CC];
__device__ float g_mu[BB*CC];
__device__ float g_rstd[BB*CC];
__device__ float g_WinT[CC*2*DD];
__device__ float g_xc[BB*DD*LLEN];
__device__ float g_zs[BB*LLEN*DD];
__device__ float g_xa[BB*DD*LLEN];
__device__ float g_xaT[BB*DD*LLEN];
__device__ float g_xsb[BB*2*LLEN*DD];      // only k=0,1 stored; k>=2 is a flip
__device__ float g_dtb[BB*KK*LLEN*DD];
__device__ float g_BC[BB*KK*LLEN*32];
__device__ float g_hend[BB*KK*NCHA*NN*DD];
__device__ float g_ap[BB*KK*NCHA*NN*DD];
__device__ float g_H0[BB*KK*NCHA*NN*DD];
__device__ float g_ysb[KK*BB*LLEN*DD];

// ---------------- K1: small GEMVs + W_in transpose + IN stats ----------------
__global__ void k_small(const float* rep, const float* Wg, const float* bg,
                        const float* Wb, const float* bb,
                        const float* Wc, const float* bc,
                        const float* Wf1, const float* bf1,
                        const float* Wf2, const float* bf2,
                        const float* Win, const float* inp)
{
    if (blockIdx.x > 0) {       // instance-norm stats, one block per (b,c)
        int bc_i = blockIdx.x - 1;
        int t = threadIdx.x;
        const float* p = inp + bc_i*LLEN;
        float s = 0.f, s2 = 0.f;
        for (int i = t; i < LLEN; i += 256) { float v = p[i]; s += v; s2 += v*v; }
        __shared__ float sh[64];
        for (int off = 16; off; off >>= 1) {
            s  += __shfl_xor_sync(0xffffffffu, s,  off);
            s2 += __shfl_xor_sync(0xffffffffu, s2, off);
        }
        int w = t >> 5, lane = t & 31;
        if (lane == 0) { sh[w] = s; sh[32 + w] = s2; }
        __syncthreads();
        if (t == 0) {
            float S = 0.f, S2 = 0.f;
            for (int i = 0; i < 8; i++) { S += sh[i]; S2 += sh[32 + i]; }
            float mu = S / (float)LLEN;
            float var = S2 / (float)LLEN - mu*mu;
            g_mu[bc_i] = mu;
            g_rstd[bc_i] = rsqrtf(var + EPSV);
        }
        return;
    }
    __shared__ float rs[BB*RR];
    __shared__ float a_sm[BB*16];
    int t = threadIdx.x;
    if (t < BB*RR) rs[t] = rep[t];
    __syncthreads();
    {
        int b = t >> 6, c = t & 63;
        float ag = 0.f, ab = 0.f;
        for (int r = 0; r < RR; r++) {
            float rv = rs[b*RR + r];
            ag += rv * Wg[c*RR + r];
            ab += rv * Wb[c*RR + r];
        }
        g_gamma[t] = ag + bg[c];
        g_beta[t]  = ab + bb[c];
    }
    for (int i = t; i < BB*DD; i += 256) {
        int b = i >> 7, d = i & 127;
        float a = 0.f;
        for (int r = 0; r < RR; r++) a += rs[b*RR + r] * Wc[d*RR + r];
        g_cond[i] = 1.0f + a + bc[d];
    }
    if (t < BB*16) {
        int b = t >> 4, j = t & 15;
        float a = 0.f;
        for (int r = 0; r < RR; r++) a += rs[b*RR + r] * Wf1[j*RR + r];
        a += bf1[j];
        a_sm[t] = a > 0.f ? a : 0.f;
    }
    __syncthreads();
    {
        int b = t >> 6, c = t & 63;
        float s = bf2[c];
        for (int j = 0; j < 16; j++) s += a_sm[b*16 + j] * Wf2[c*16 + j];
        g_att[t] = 1.0f / (1.0f + __expf(-s));
    }
    for (int i = t; i < 2*DD*CC; i += 256) {
        int o = i / CC, c = i - o*CC;
        g_WinT[c*(2*DD) + o] = Win[i];
    }
}

// ---------------- K3: FiLM + in-projection GEMM ----------------
__global__ void __launch_bounds__(256) k_inproj(const float* inp)
{
    __shared__ float buf[256*33];
    int bx = blockIdx.x;
    int b  = bx >> 7;
    int l0 = (bx & 127) * 32;
    int t = threadIdx.x;
    for (int i = t; i < CC*32; i += 256) {
        int c = i >> 5, li = i & 31;
        int bc = b*CC + c;
        float v  = inp[bc*LLEN + l0 + li];
        float sc = g_rstd[bc] * (1.0f + g_gamma[bc]);
        float bi = g_beta[bc] - g_mu[bc]*sc;
        buf[c*36 + li] = v*sc + bi;
    }
    __syncthreads();
    int o = t;
    float acc[32];
#pragma unroll
    for (int li = 0; li < 32; li++) acc[li] = 0.f;
    for (int c = 0; c < CC; c++) {
        float w = g_WinT[c*256 + o];
        const float4* xp = (const float4*)&buf[c*36];
#pragma unroll
        for (int q = 0; q < 8; q++) {
            float4 x4 = xp[q];
            acc[q*4+0] += w*x4.x; acc[q*4+1] += w*x4.y;
            acc[q*4+2] += w*x4.z; acc[q*4+3] += w*x4.w;
        }
    }
    if (o >= DD) {
#pragma unroll
        for (int li = 0; li < 32; li++) {
            float z = acc[li];
            acc[li] = z / (1.0f + __expf(-z));
        }
    }
    __syncthreads();
#pragma unroll
    for (int li = 0; li < 32; li++) buf[o*33 + li] = acc[li];
    __syncthreads();
    for (int i = t; i < DD*32; i += 256) {
        int d = i >> 5, li = i & 31;
        g_xc[(b*DD + d)*LLEN + l0 + li] = buf[d*33 + li];
    }
    for (int i = t; i < DD*32; i += 256) {
        int li = i >> 7, zd = i & 127;
        g_zs[(b*LLEN + l0 + li)*DD + zd] = buf[(128 + zd)*33 + li];
    }
}

// ---------------- K4: depthwise 3x3 conv + silu (+ transpose) ----------------
__global__ void __launch_bounds__(256) k_conv(const float* cw, const float* cb)
{
    int bd = blockIdx.x;
    int d = bd & 127;
    __shared__ float insm[66*66];
    __shared__ float osm[64*65];
    int t = threadIdx.x;
    if (t < 66) { insm[t] = 0.f; insm[65*66 + t] = 0.f; }
    if (t < 64) { insm[(t+1)*66] = 0.f; insm[(t+1)*66 + 65] = 0.f; }
    const float* src = &g_xc[bd*LLEN];
    for (int i = t; i < LLEN; i += 256) {
        int h = i >> 6, w = i & 63;
        insm[(h+1)*66 + (w+1)] = src[i];
    }
    float wv[9];
#pragma unroll
    for (int i = 0; i < 9; i++) wv[i] = cw[d*9 + i];
    float bias = cb[d];
    __syncthreads();
    float* dsta = &g_xa[bd*LLEN];
    for (int i = t; i < LLEN; i += 256) {
        int h = i >> 6, w = i & 63;
        float a = bias;
#pragma unroll
        for (int ki = 0; ki < 3; ki++)
#pragma unroll
            for (int kj = 0; kj < 3; kj++)
                a += insm[(h+ki)*66 + (w+kj)] * wv[ki*3+kj];
        float v = a / (1.0f + __expf(-a));
        dsta[i] = v;
        osm[h*65 + w] = v;
    }
    __syncthreads();
    float* dstt = &g_xaT[bd*LLEN];
    for (int i = t; i < LLEN; i += 256) {
        int h = i & 63, w = i >> 6;
        dstt[i] = osm[h*65 + w];
    }
}

// ---- K5: x_dbl GEMM + dt-proj + FUSED phase-A scan (256 thr, 2 sub-chunks) --
__global__ void __launch_bounds__(256) k_xdbl(const float* xpw, const float* dtw,
                                              const float* dtbp, const float* Alogs)
{
    extern __shared__ float dsm[];
    float* xsT  = dsm;                    // [64][132], live through the scan
    float* xdbl = dsm + 64*132;           // [36][68]
    float* Btr  = xdbl + 36*68;           // [64][24]: 0-15 = B, 16-19 = dt-rank
    int bx = blockIdx.x;                  // 1024 blocks
    int b  = bx >> 8;
    int k  = (bx >> 6) & 3;
    int lt = bx & 63;
    int bk = b*KK + k;
    int l0 = lt*64;
    int t = threadIdx.x;
    const float* src = (k & 1) ? &g_xaT[b*DD*LLEN] : &g_xa[b*DD*LLEN];
    bool flip = (k >= 2);
    for (int i = t; i < DD*64; i += 256) {        // coalesced over l
        int d = i >> 6, li = i & 63;
        int l = l0 + li;
        int m = flip ? (LLEN - 1 - l) : l;
        xsT[li*132 + d] = src[d*LLEN + m];
    }
    __syncthreads();
    if (k < 2) {
        int bk2 = b*2 + k;
        for (int i = t; i < DD*64; i += 256) {
            int li = i >> 7, d = i & 127;
            g_xsb[(bk2*LLEN + l0 + li)*DD + d] = xsT[li*132 + d];
        }
    }
    // GEMM: g = rows group (9 rows), li = single l column
    int g = t >> 6, li = t & 63;
    float acc[9];
    {
#pragma unroll
        for (int r = 0; r < 9; r++) acc[r] = 0.f;
        const float4* xp = (const float4*)&xsT[li*132];
        const float4* wb = (const float4*)(xpw + k*36*128 + g*9*128);
#pragma unroll 4
        for (int d4 = 0; d4 < 32; d4++) {
            float4 x4 = xp[d4];
#pragma unroll
            for (int r = 0; r < 9; r++) {
                float4 w4 = __ldg(&wb[r*32 + d4]);
                acc[r] += x4.x*w4.x + x4.y*w4.y + x4.z*w4.z + x4.w*w4.w;
            }
        }
    }
    // stage x_dbl (fresh smem region; no pre-sync needed)
#pragma unroll
    for (int r = 0; r < 9; r++) xdbl[(g*9 + r)*68 + li] = acc[r];
    __syncthreads();
    // Btr build + g_BC write
    for (int i = t; i < 16*64; i += 256) {        // B rows -> Btr
        int n = i >> 6, li2 = i & 63;
        Btr[li2*24 + n] = xdbl[(4 + n)*68 + li2];
    }
    for (int i = t; i < 4*64; i += 256) {         // dt-rank rows -> Btr
        int r = i >> 6, li2 = i & 63;
        Btr[li2*24 + 16 + r] = xdbl[r*68 + li2];
    }
    for (int i = t; i < 64*32; i += 256) {        // B|C -> (bk,l,32) for scanC
        int li2 = i >> 5, j = i & 31;
        g_BC[(bk*LLEN + l0 + li2)*32 + j] = xdbl[(4 + j)*68 + li2];
    }
    __syncthreads();
    // ---- fused phase-A scan: 2 sub-chunks of 32 steps ----
    int sub = t >> 7;
    int d = t & 127;
    float a[NN];
    bool fast = true;
#pragma unroll
    for (int n = 0; n < NN; n++) {
        a[n] = -__expf(Alogs[(k*DD + d)*NN + n]);
        fast = fast && (fabsf(a[n] + (float)(n+1)) < 1e-3f);
    }
    float4 w4 = *(const float4*)&dtw[(k*DD + d)*4];
    float bsv = dtbp[k*DD + d];
    int sbase = sub*32;
    float* dtdst = &g_dtb[(bk*LLEN + l0 + sbase)*DD + d];
    float S = 0.f;
    int cb = bk*NCHA + lt*2 + sub;
    if (fast) {
        u64 h2[8];
#pragma unroll
        for (int j = 0; j < 8; j++) h2[j] = 0ull;
#pragma unroll 2
        for (int s = 0; s < 32; s++) {
            float4 dr = *(const float4*)&Btr[(sbase + s)*24 + 16];
            float sv = bsv + dr.x*w4.x + dr.y*w4.y + dr.z*w4.z + dr.w*w4.w;
            float dt = softplus_f(sv);
            dtdst[s*DD] = dt;
            float x = xsT[(sbase + s)*132 + d];
            float u = dt*x;
            S += dt;
            u64 u2 = pk2(u, u);
            float r = __expf(-dt);
            u64 p2[8];
            pow_tree2(r, p2);
            const ulonglong2* bc2 = (const ulonglong2*)&Btr[(sbase + s)*24];
#pragma unroll
            for (int j = 0; j < 4; j++) {
                ulonglong2 bp = bc2[j];
                h2[2*j]   = fma2(h2[2*j],   p2[2*j],   mul2(u2, bp.x));
                h2[2*j+1] = fma2(h2[2*j+1], p2[2*j+1], mul2(u2, bp.y));
            }
        }
        float q = __expf(-S);
        u64 ap2[8];
        pow_tree2(q, ap2);
#pragma unroll
        for (int j = 0; j < 8; j++) {
            float h0, h1, a0, a1;
            upk2(h2[j], h0, h1);
            upk2(ap2[j], a0, a1);
            g_hend[(cb*NN + 2*j  )*DD + d] = h0;
            g_hend[(cb*NN + 2*j+1)*DD + d] = h1;
            g_ap[(cb*NN + 2*j  )*DD + d] = a0;
            g_ap[(cb*NN + 2*j+1)*DD + d] = a1;
        }
    } else {
        float h[NN];
#pragma unroll
        for (int n = 0; n < NN; n++) h[n] = 0.f;
        for (int s = 0; s < 32; s++) {
            float4 dr = *(const float4*)&Btr[(sbase + s)*24 + 16];
            float sv = bsv + dr.x*w4.x + dr.y*w4.y + dr.z*w4.z + dr.w*w4.w;
            float dt = softplus_f(sv);
            dtdst[s*DD] = dt;
            float x = xsT[(sbase + s)*132 + d];
            float u = dt*x;
            S += dt;
            const float* bb = &Btr[(sbase + s)*24];
#pragma unroll
            for (int n = 0; n < NN; n++) h[n] = h[n]*__expf(dt*a[n]) + u*bb[n];
        }
#pragma unroll
        for (int n = 0; n < NN; n++) {
            g_hend[(cb*NN + n)*DD + d] = h[n];
            g_ap[(cb*NN + n)*DD + d] = __expf(a[n]*S);
        }
    }
}

// ---------------- K7: scan phase B (cross-chunk prefix, MLP=8) ---------------
__global__ void __launch_bounds__(128) k_scanB()
{
    int bk = blockIdx.x >> 4;
    int n  = blockIdx.x & 15;
    int d = threadIdx.x;
    const int stride = NN*DD;
    int base = ((bk*NCHA)*NN + n)*DD + d;
    float Hv = 0.f;
    for (int c0 = 0; c0 < NCHA; c0 += 8) {
        float ap[8], he[8];
#pragma unroll
        for (int j = 0; j < 8; j++) {
            ap[j] = g_ap[base + (c0+j)*stride];
            he[j] = g_hend[base + (c0+j)*stride];
        }
#pragma unroll
        for (int j = 0; j < 8; j++) {
            g_H0[base + (c0+j)*stride] = Hv;
            Hv = Hv*ap[j] + he[j];
        }
    }
}

// ---------------- K8: scan phase C (rescan + y + scatter, packed f32x2) ------
__global__ void __launch_bounds__(128) k_scanC(const float* Alogs, const float* Ds)
{
    __shared__ float smBC[CHL*32];
    int bk = blockIdx.x >> 6;
    int ch = blockIdx.x & 63;
    int k = bk & 3;
    int b = bk >> 2;
    int d = threadIdx.x;
    int base = ch*CHL;
    {
        const float4* src4 = (const float4*)&g_BC[(bk*LLEN + base)*32];
        float4* dst4 = (float4*)smBC;
        for (int i = d; i < CHL*8; i += 128) dst4[i] = src4[i];
    }
    float a[NN];
    bool fast = true;
#pragma unroll
    for (int n = 0; n < NN; n++) {
        a[n] = -__expf(Alogs[(k*DD + d)*NN + n]);
        fast = fast && (fabsf(a[n] + (float)(n+1)) < 1e-3f);
    }
    int cb = bk*NCHA + ch*2;     // even sub-chunk's H0; rescan covers both
    float Dv = Ds[k*DD + d];
    const float* dtp = &g_dtb[(bk*LLEN + base)*DD + d];
    int xrow = (b*2 + (k & 1))*LLEN;
    bool flip = (k >= 2);
    const float* xp;
    int xstep;
    if (!flip) { xp = &g_xsb[(xrow + base)*DD + d]; xstep = DD; }
    else       { xp = &g_xsb[(xrow + (LLEN-1-base))*DD + d]; xstep = -DD; }
    float* dst = &g_ysb[k*BKLD + b*LLEN*DD];
    __syncthreads();
    if (fast) {
        u64 h2[8];
#pragma unroll
        for (int j = 0; j < 8; j++)
            h2[j] = pk2(g_H0[(cb*NN + 2*j)*DD + d], g_H0[(cb*NN + 2*j+1)*DD + d]);
        float dt_n = dtp[0], x_n = xp[0];
#pragma unroll 2
        for (int s = 0; s < CHL; s++) {
            float dt = dt_n, x = x_n;
            if (s + 1 < CHL) { dt_n = dtp[(s+1)*DD]; x_n = xp[(s+1)*xstep]; }
            float u = dt*x;
            u64 u2 = pk2(u, u);
            float r = __expf(-dt);
            u64 p2[8];
            pow_tree2(r, p2);
            const ulonglong2* bc2 = (const ulonglong2*)&smBC[s*32];
            u64 ya = 0ull, yb = 0ull;
#pragma unroll
            for (int j = 0; j < 4; j++) {
                ulonglong2 bp = bc2[j];
                ulonglong2 cp = bc2[4 + j];
                h2[2*j]   = fma2(h2[2*j],   p2[2*j],   mul2(u2, bp.x));
                ya = fma2(h2[2*j], cp.x, ya);
                h2[2*j+1] = fma2(h2[2*j+1], p2[2*j+1], mul2(u2, bp.y));
                yb = fma2(h2[2*j+1], cp.y, yb);
            }
            float y0, y1, y2, y3;
            upk2(ya, y0, y1);
            upk2(yb, y2, y3);
            float ys = (y0 + y1) + (y2 + y3) + x*Dv;
            int sa = base + s;
            int lrow;
            if (k == 0)      lrow = sa;
            else if (k == 1) lrow = ((sa & 63) << 6) | (sa >> 6);
            else if (k == 2) lrow = LLEN - 1 - sa;
            else { int m = LLEN - 1 - sa; lrow = ((m & 63) << 6) | (m >> 6); }
            dst[lrow*DD + d] = ys;
        }
    } else {
        float h[NN];
#pragma unroll
        for (int n = 0; n < NN; n++) h[n] = g_H0[(cb*NN + n)*DD + d];
        for (int s = 0; s < CHL; s++) {
            float dt = dtp[s*DD];
            float x  = xp[s*xstep];
            float u = dt*x;
            const float* bb = &smBC[s*32];
            const float* cc = &smBC[s*32 + 16];
            float y0 = 0.f, y1 = 0.f, y2 = 0.f, y3 = 0.f;
#pragma unroll
            for (int n = 0; n < NN; n += 4) {
                h[n+0] = h[n+0]*__expf(dt*a[n+0]) + u*bb[n+0]; y0 += h[n+0]*cc[n+0];
                h[n+1] = h[n+1]*__expf(dt*a[n+1]) + u*bb[n+1]; y1 += h[n+1]*cc[n+1];
                h[n+2] = h[n+2]*__expf(dt*a[n+2]) + u*bb[n+2]; y2 += h[n+2]*cc[n+2];
                h[n+3] = h[n+3]*__expf(dt*a[n+3]) + u*bb[n+3]; y3 += h[n+3]*cc[n+3];
            }
            float ys = (y0 + y1) + (y2 + y3) + x*Dv;
            int sa = base + s;
            int lrow;
            if (k == 0)      lrow = sa;
            else if (k == 1) lrow = ((sa & 63) << 6) | (sa >> 6);
            else if (k == 2) lrow = LLEN - 1 - sa;
            else { int m = LLEN - 1 - sa; lrow = ((m & 63) << 6) | (m >> 6); }
            dst[lrow*DD + d] = ys;
        }
    }
}

// ---------------- K9: combine + LN + gates + out-proj + residual -------------
__global__ void __launch_bounds__(256) k_final(const float* inp, const float* lnw,
                                               const float* lnb, const float* Wout,
                                               float* out)
{
    __shared__ float Wsm[64*132];
    __shared__ float val_sm[8*128];
    __shared__ float osm[64*8];
    int t = threadIdx.x;
    int b = blockIdx.x >> 7;
    int lbase = (blockIdx.x & 127) * 32;
    for (int i = t; i < 64*32; i += 256) {
        int c = i >> 5, q = i & 31;
        *(float4*)&Wsm[c*132 + q*4] = ((const float4*)Wout)[i];
    }
    __syncthreads();
    int w = t >> 5, lane = t & 31;
    float4 lw = ((const float4*)lnw)[lane];
    float4 lb = ((const float4*)lnb)[lane];
    float4 cd = *(const float4*)&g_cond[b*DD + lane*4];
    for (int it = 0; it < 4; it++) {
        int l0 = lbase + it*8;
        int l = l0 + w;
        int off = (b*LLEN + l)*DD + lane*4;
        float4 y4;
        {
            float4 a0 = *(const float4*)&g_ysb[0*BKLD + off];
            float4 a1 = *(const float4*)&g_ysb[1*BKLD + off];
            float4 a2 = *(const float4*)&g_ysb[2*BKLD + off];
            float4 a3 = *(const float4*)&g_ysb[3*BKLD + off];
            y4.x = a0.x + a1.x + a2.x + a3.x;
            y4.y = a0.y + a1.y + a2.y + a3.y;
            y4.z = a0.z + a1.z + a2.z + a3.z;
            y4.w = a0.w + a1.w + a2.w + a3.w;
        }
        float s1 = y4.x + y4.y + y4.z + y4.w;
        float s2 = y4.x*y4.x + y4.y*y4.y + y4.z*y4.z + y4.w*y4.w;
        for (int o2 = 16; o2; o2 >>= 1) {
            s1 += __shfl_xor_sync(0xffffffffu, s1, o2);
            s2 += __shfl_xor_sync(0xffffffffu, s2, o2);
        }
        float mean = s1 * (1.f/128.f);
        float var  = s2 * (1.f/128.f) - mean*mean;
        float rstd = rsqrtf(var + EPSV);
        float4 z4 = *(const float4*)&g_zs[off];
        float4 v4;
        v4.x = ((y4.x - mean)*rstd*lw.x + lb.x) * cd.x * z4.x;
        v4.y = ((y4.y - mean)*rstd*lw.y + lb.y) * cd.y * z4.y;
        v4.z = ((y4.z - mean)*rstd*lw.z + lb.z) * cd.z * z4.z;
        v4.w = ((y4.w - mean)*rstd*lw.w + lb.w) * cd.w * z4.w;
        *(float4*)&val_sm[w*128 + lane*4] = v4;
        __syncwarp();
        float acc0 = 0.f, acc1 = 0.f;
        const float4* vp = (const float4*)&val_sm[w*128];
        const float4* w0 = (const float4*)&Wsm[lane*132];
        const float4* w1 = (const float4*)&Wsm[(lane+32)*132];
#pragma unroll 8
        for (int q = 0; q < 32; q++) {
            float4 v = vp[q];
            float4 wa = w0[q];
            float4 wb = w1[q];
            acc0 += v.x*wa.x + v.y*wa.y + v.z*wa.z + v.w*wa.w;
            acc1 += v.x*wb.x + v.y*wb.y + v.z*wb.z + v.w*wb.w;
        }
        osm[lane*8 + w] = acc0;
        osm[(lane+32)*8 + w] = acc1;
        __syncthreads();
        for (int i = t; i < 64*8; i += 256) {
            int c = i >> 3, li = i & 7;
            int gi = (b*CC + c)*LLEN + l0 + li;
            out[gi] = osm[c*8 + li] + inp[gi]*g_att[b*CC + c];
        }
        __syncthreads();
    }
}

extern "C" void kernel_launch(void* const* d_in, const int* in_sizes, int n_in,
                              void* d_out, int out_size)
{
    const float* inp   = (const float*)d_in[0];
    const float* rep   = (const float*)d_in[1];
    const float* Wg    = (const float*)d_in[2];
    const float* bg    = (const float*)d_in[3];
    const float* Wb    = (const float*)d_in[4];
    const float* bbp   = (const float*)d_in[5];
    const float* Win   = (const float*)d_in[6];
    const float* cw    = (const float*)d_in[7];
    const float* cb    = (const float*)d_in[8];
    const float* xpw   = (const float*)d_in[9];
    const float* dtw   = (const float*)d_in[10];
    const float* dtbp  = (const float*)d_in[11];
    const float* Alogs = (const float*)d_in[12];
    const float* Ds    = (const float*)d_in[13];
    const float* lnw   = (const float*)d_in[14];
    const float* lnb   = (const float*)d_in[15];
    const float* Wc    = (const float*)d_in[16];
    const float* bc    = (const float*)d_in[17];
    const float* Wout  = (const float*)d_in[18];
    const float* Wf1   = (const float*)d_in[19];
    const float* bf1   = (const float*)d_in[20];
    const float* Wf2   = (const float*)d_in[21];
    const float* bf2   = (const float*)d_in[22];
    float* out = (float*)d_out;

    cudaFuncSetAttribute(k_xdbl, cudaFuncAttributeMaxDynamicSharedMemorySize,
                         XDBL_SMEM * (int)sizeof(float));

    k_small<<<1 + BB*CC, 256>>>(rep, Wg, bg, Wb, bbp, Wc, bc, Wf1, bf1, Wf2, bf2, Win, inp);
    k_inproj<<<BB*128, 256>>>(inp);
    k_conv<<<BB*DD, 256>>>(cw, cb);
    k_xdbl<<<BB*KK*64, 256, XDBL_SMEM * (int)sizeof(float)>>>(xpw, dtw, dtbp, Alogs);
    k_scanB<<<BB*KK*NN, 128>>>();
    k_scanC<<<BB*KK*64, 128>>>(Alogs, Ds);
    k_final<<<BB*128, 256>>>(inp, lnw, lnb, Wout, out);
}

// round 11
// speedup vs baseline: 1.0400x; 1.0400x over previous
#include <cuda_runtime.h>
#include <math.h>

#define BB 4
#define CC 64
#define HH 64
#define WW 64
#define LLEN 4096
#define RR 64
#define DD 128
#define KK 4
#define NN 16
#define NCHA 128              // phase-A sub-chunks per (b,k), 32 steps each
#define CHL 64                // scanC chunk length (2 sub-chunks)
#define EPSV 1e-5f
#define BKLD (BB*LLEN*DD)
// smem: xsT [64][132] + Wp[36][128] (reused as xdbl[36][68] + Btr[64][24])
#define XDBL_SMEM (64*132 + 36*128)

typedef unsigned long long u64;
typedef unsigned int u32;

__device__ __forceinline__ u64 pk2(float lo, float hi) {
    u64 r; u32 a = __float_as_uint(lo), b = __float_as_uint(hi);
    asm("mov.b64 %0, {%1, %2};" : "=l"(r) : "r"(a), "r"(b));
    return r;
}
__device__ __forceinline__ u64 fma2(u64 a, u64 b, u64 c) {
    u64 d; asm("fma.rn.f32x2 %0, %1, %2, %3;" : "=l"(d) : "l"(a), "l"(b), "l"(c));
    return d;
}
__device__ __forceinline__ u64 mul2(u64 a, u64 b) {
    u64 d; asm("mul.rn.f32x2 %0, %1, %2;" : "=l"(d) : "l"(a), "l"(b));
    return d;
}
__device__ __forceinline__ void upk2(u64 v, float& lo, float& hi) {
    u32 a, b; asm("mov.b64 {%0, %1}, %2;" : "=r"(a), "=r"(b) : "l"(v));
    lo = __uint_as_float(a); hi = __uint_as_float(b);
}
// p2[j] = {r^(2j+1), r^(2j+2)}, dependency depth ~4
__device__ __forceinline__ void pow_tree2(float r, u64* p2) {
    float r2 = r*r, r4 = r2*r2, r8 = r4*r4;
    u64 q0 = pk2(r, r2), s2 = pk2(r2, r2), s4 = pk2(r4, r4), s8 = pk2(r8, r8);
    p2[0] = q0;
    p2[1] = mul2(q0, s2);
    p2[2] = mul2(q0, s4);
    p2[3] = mul2(p2[1], s4);
    p2[4] = mul2(q0, s8);
    p2[5] = mul2(p2[1], s8);
    p2[6] = mul2(p2[2], s8);
    p2[7] = mul2(p2[3], s8);
}
// fast softplus: branch-light, MUFU-based
__device__ __forceinline__ float softplus_f(float s) {
    float as = fabsf(s);
    float sp = fmaxf(s, 0.f) + __logf(1.f + __expf(-as));
    return (s > 20.f) ? s : sp;
}

// ---------------- scratch ----------------
__device__ float g_gamma[BB*CC];
__device__ float g_beta[BB*CC];
__device__ float g_cond[BB*DD];
__device__ float g_att[BB*CC];
__device__ float g_mu[BB*CC];
__device__ float g_rstd[BB*CC];
__device__ float g_WinT[CC*2*DD];
__device__ float g_xc[BB*DD*LLEN];
__device__ float g_zs[BB*LLEN*DD];
__device__ float g_xa[BB*DD*LLEN];
__device__ float g_xaT[BB*DD*LLEN];
__device__ float g_xsb[BB*2*LLEN*DD];      // only k=0,1 stored; k>=2 is a flip
__device__ float g_dtb[BB*KK*LLEN*DD];
__device__ float g_BC[BB*KK*LLEN*32];
__device__ float g_hend[BB*KK*NCHA*NN*DD];
__device__ float g_ap[BB*KK*NCHA*NN*DD];
__device__ float g_H0[BB*KK*NCHA*NN*DD];
__device__ float g_ysb[KK*BB*LLEN*DD];

// ---------------- K1: small GEMVs + W_in transpose + IN stats ----------------
__global__ void k_small(const float* rep, const float* Wg, const float* bg,
                        const float* Wb, const float* bb,
                        const float* Wc, const float* bc,
                        const float* Wf1, const float* bf1,
                        const float* Wf2, const float* bf2,
                        const float* Win, const float* inp)
{
    if (blockIdx.x > 0) {       // instance-norm stats, one block per (b,c)
        int bc_i = blockIdx.x - 1;
        int t = threadIdx.x;
        const float* p = inp + bc_i*LLEN;
        float s = 0.f, s2 = 0.f;
        for (int i = t; i < LLEN; i += 256) { float v = p[i]; s += v; s2 += v*v; }
        __shared__ float sh[64];
        for (int off = 16; off; off >>= 1) {
            s  += __shfl_xor_sync(0xffffffffu, s,  off);
            s2 += __shfl_xor_sync(0xffffffffu, s2, off);
        }
        int w = t >> 5, lane = t & 31;
        if (lane == 0) { sh[w] = s; sh[32 + w] = s2; }
        __syncthreads();
        if (t == 0) {
            float S = 0.f, S2 = 0.f;
            for (int i = 0; i < 8; i++) { S += sh[i]; S2 += sh[32 + i]; }
            float mu = S / (float)LLEN;
            float var = S2 / (float)LLEN - mu*mu;
            g_mu[bc_i] = mu;
            g_rstd[bc_i] = rsqrtf(var + EPSV);
        }
        return;
    }
    __shared__ float rs[BB*RR];
    __shared__ float a_sm[BB*16];
    int t = threadIdx.x;
    if (t < BB*RR) rs[t] = rep[t];
    __syncthreads();
    {
        int b = t >> 6, c = t & 63;
        float ag = 0.f, ab = 0.f;
        for (int r = 0; r < RR; r++) {
            float rv = rs[b*RR + r];
            ag += rv * Wg[c*RR + r];
            ab += rv * Wb[c*RR + r];
        }
        g_gamma[t] = ag + bg[c];
        g_beta[t]  = ab + bb[c];
    }
    for (int i = t; i < BB*DD; i += 256) {
        int b = i >> 7, d = i & 127;
        float a = 0.f;
        for (int r = 0; r < RR; r++) a += rs[b*RR + r] * Wc[d*RR + r];
        g_cond[i] = 1.0f + a + bc[d];
    }
    if (t < BB*16) {
        int b = t >> 4, j = t & 15;
        float a = 0.f;
        for (int r = 0; r < RR; r++) a += rs[b*RR + r] * Wf1[j*RR + r];
        a += bf1[j];
        a_sm[t] = a > 0.f ? a : 0.f;
    }
    __syncthreads();
    {
        int b = t >> 6, c = t & 63;
        float s = bf2[c];
        for (int j = 0; j < 16; j++) s += a_sm[b*16 + j] * Wf2[c*16 + j];
        g_att[t] = 1.0f / (1.0f + __expf(-s));
    }
    for (int i = t; i < 2*DD*CC; i += 256) {
        int o = i / CC, c = i - o*CC;
        g_WinT[c*(2*DD) + o] = Win[i];
    }
}

// ---------------- K3: FiLM + in-projection GEMM ----------------
__global__ void __launch_bounds__(256) k_inproj(const float* inp)
{
    __shared__ float buf[256*33];
    int bx = blockIdx.x;
    int b  = bx >> 7;
    int l0 = (bx & 127) * 32;
    int t = threadIdx.x;
    for (int i = t; i < CC*32; i += 256) {
        int c = i >> 5, li = i & 31;
        int bc = b*CC + c;
        float v  = inp[bc*LLEN + l0 + li];
        float sc = g_rstd[bc] * (1.0f + g_gamma[bc]);
        float bi = g_beta[bc] - g_mu[bc]*sc;
        buf[c*36 + li] = v*sc + bi;
    }
    __syncthreads();
    int o = t;
    float acc[32];
#pragma unroll
    for (int li = 0; li < 32; li++) acc[li] = 0.f;
    for (int c = 0; c < CC; c++) {
        float w = g_WinT[c*256 + o];
        const float4* xp = (const float4*)&buf[c*36];
#pragma unroll
        for (int q = 0; q < 8; q++) {
            float4 x4 = xp[q];
            acc[q*4+0] += w*x4.x; acc[q*4+1] += w*x4.y;
            acc[q*4+2] += w*x4.z; acc[q*4+3] += w*x4.w;
        }
    }
    if (o >= DD) {
#pragma unroll
        for (int li = 0; li < 32; li++) {
            float z = acc[li];
            acc[li] = z / (1.0f + __expf(-z));
        }
    }
    __syncthreads();
#pragma unroll
    for (int li = 0; li < 32; li++) buf[o*33 + li] = acc[li];
    __syncthreads();
    for (int i = t; i < DD*32; i += 256) {
        int d = i >> 5, li = i & 31;
        g_xc[(b*DD + d)*LLEN + l0 + li] = buf[d*33 + li];
    }
    for (int i = t; i < DD*32; i += 256) {
        int li = i >> 7, zd = i & 127;
        g_zs[(b*LLEN + l0 + li)*DD + zd] = buf[(128 + zd)*33 + li];
    }
}

// ---------------- K4: depthwise 3x3 conv + silu (+ transpose) ----------------
__global__ void __launch_bounds__(256) k_conv(const float* cw, const float* cb)
{
    int bd = blockIdx.x;
    int d = bd & 127;
    __shared__ float insm[66*66];
    __shared__ float osm[64*65];
    int t = threadIdx.x;
    if (t < 66) { insm[t] = 0.f; insm[65*66 + t] = 0.f; }
    if (t < 64) { insm[(t+1)*66] = 0.f; insm[(t+1)*66 + 65] = 0.f; }
    const float* src = &g_xc[bd*LLEN];
    for (int i = t; i < LLEN; i += 256) {
        int h = i >> 6, w = i & 63;
        insm[(h+1)*66 + (w+1)] = src[i];
    }
    float wv[9];
#pragma unroll
    for (int i = 0; i < 9; i++) wv[i] = cw[d*9 + i];
    float bias = cb[d];
    __syncthreads();
    float* dsta = &g_xa[bd*LLEN];
    for (int i = t; i < LLEN; i += 256) {
        int h = i >> 6, w = i & 63;
        float a = bias;
#pragma unroll
        for (int ki = 0; ki < 3; ki++)
#pragma unroll
            for (int kj = 0; kj < 3; kj++)
                a += insm[(h+ki)*66 + (w+kj)] * wv[ki*3+kj];
        float v = a / (1.0f + __expf(-a));
        dsta[i] = v;
        osm[h*65 + w] = v;
    }
    __syncthreads();
    float* dstt = &g_xaT[bd*LLEN];
    for (int i = t; i < LLEN; i += 256) {
        int h = i & 63, w = i >> 6;
        dstt[i] = osm[h*65 + w];
    }
}

// ---- K5: x_dbl GEMM (smem weights) + dt-proj + fused phase-A scan -----------
// 256 threads: GEMM g=t>>6 (9 rows) x li=t&63; scan 2 sub-chunks of 32 steps.
__global__ void __launch_bounds__(256, 4) k_xdbl(const float* xpw, const float* dtw,
                                                 const float* dtbp, const float* Alogs)
{
    extern __shared__ float dsm[];
    float* xsT  = dsm;                    // [64][132], live through the scan
    float* Wp   = dsm + 64*132;           // [36][128]; dead after GEMM -> reused:
    float* xdbl = Wp;                     //   [36][68]  (2448 floats)
    float* Btr  = Wp + 2448;              //   [64][24]: 0-15 = B, 16-19 = dt-rank
    int bx = blockIdx.x;                  // 1024 blocks
    int b  = bx >> 8;
    int k  = (bx >> 6) & 3;
    int lt = bx & 63;
    int bk = b*KK + k;
    int l0 = lt*64;
    int t = threadIdx.x;
    {   // float4 weight staging into smem
        const float4* wsrc = (const float4*)(xpw + k*36*128);
        float4* wdst = (float4*)Wp;
        for (int i = t; i < 36*32; i += 256) wdst[i] = wsrc[i];
    }
    const float* src = (k & 1) ? &g_xaT[b*DD*LLEN] : &g_xa[b*DD*LLEN];
    bool flip = (k >= 2);
    for (int i = t; i < DD*64; i += 256) {        // coalesced over l
        int d = i >> 6, li = i & 63;
        int l = l0 + li;
        int m = flip ? (LLEN - 1 - l) : l;
        xsT[li*132 + d] = src[d*LLEN + m];
    }
    __syncthreads();
    if (k < 2) {
        int bk2 = b*2 + k;
        for (int i = t; i < DD*64; i += 256) {
            int li = i >> 7, d = i & 127;
            g_xsb[(bk2*LLEN + l0 + li)*DD + d] = xsT[li*132 + d];
        }
    }
    // GEMM: g = row group (9 rows), li = single l column, weights via smem broadcast
    int g = t >> 6, li = t & 63;
    float acc[9];
    {
#pragma unroll
        for (int r = 0; r < 9; r++) acc[r] = 0.f;
        const float4* xp = (const float4*)&xsT[li*132];
        const float4* wb = (const float4*)&Wp[g*9*128];
#pragma unroll 4
        for (int d4 = 0; d4 < 32; d4++) {
            float4 x4 = xp[d4];
#pragma unroll
            for (int r = 0; r < 9; r++) {
                float4 w4 = wb[r*32 + d4];
                acc[r] += x4.x*w4.x + x4.y*w4.y + x4.z*w4.z + x4.w*w4.w;
            }
        }
    }
    __syncthreads();          // all Wp reads done; safe to overwrite with xdbl
#pragma unroll
    for (int r = 0; r < 9; r++) xdbl[(g*9 + r)*68 + li] = acc[r];
    __syncthreads();
    // Btr build + g_BC write
    for (int i = t; i < 16*64; i += 256) {        // B rows -> Btr
        int n = i >> 6, li2 = i & 63;
        Btr[li2*24 + n] = xdbl[(4 + n)*68 + li2];
    }
    for (int i = t; i < 4*64; i += 256) {         // dt-rank rows -> Btr
        int r = i >> 6, li2 = i & 63;
        Btr[li2*24 + 16 + r] = xdbl[r*68 + li2];
    }
    for (int i = t; i < 64*32; i += 256) {        // B|C -> (bk,l,32) for scanC
        int li2 = i >> 5, j = i & 31;
        g_BC[(bk*LLEN + l0 + li2)*32 + j] = xdbl[(4 + j)*68 + li2];
    }
    __syncthreads();
    // ---- fused phase-A scan: 2 sub-chunks of 32 steps ----
    int sub = t >> 7;
    int d = t & 127;
    float a[NN];
    bool fast = true;
#pragma unroll
    for (int n = 0; n < NN; n++) {
        a[n] = -__expf(Alogs[(k*DD + d)*NN + n]);
        fast = fast && (fabsf(a[n] + (float)(n+1)) < 1e-3f);
    }
    float4 w4 = *(const float4*)&dtw[(k*DD + d)*4];
    float bsv = dtbp[k*DD + d];
    int sbase = sub*32;
    float* dtdst = &g_dtb[(bk*LLEN + l0 + sbase)*DD + d];
    float S = 0.f;
    int cb = bk*NCHA + lt*2 + sub;
    if (fast) {
        u64 h2[8];
#pragma unroll
        for (int j = 0; j < 8; j++) h2[j] = 0ull;
#pragma unroll 2
        for (int s = 0; s < 32; s++) {
            float4 dr = *(const float4*)&Btr[(sbase + s)*24 + 16];
            float sv = bsv + dr.x*w4.x + dr.y*w4.y + dr.z*w4.z + dr.w*w4.w;
            float dt = softplus_f(sv);
            dtdst[s*DD] = dt;
            float x = xsT[(sbase + s)*132 + d];
            float u = dt*x;
            S += dt;
            u64 u2 = pk2(u, u);
            float r = __expf(-dt);
            u64 p2[8];
            pow_tree2(r, p2);
            const ulonglong2* bc2 = (const ulonglong2*)&Btr[(sbase + s)*24];
#pragma unroll
            for (int j = 0; j < 4; j++) {
                ulonglong2 bp = bc2[j];
                h2[2*j]   = fma2(h2[2*j],   p2[2*j],   mul2(u2, bp.x));
                h2[2*j+1] = fma2(h2[2*j+1], p2[2*j+1], mul2(u2, bp.y));
            }
        }
        float q = __expf(-S);
        u64 ap2[8];
        pow_tree2(q, ap2);
#pragma unroll
        for (int j = 0; j < 8; j++) {
            float h0, h1, a0, a1;
            upk2(h2[j], h0, h1);
            upk2(ap2[j], a0, a1);
            g_hend[(cb*NN + 2*j  )*DD + d] = h0;
            g_hend[(cb*NN + 2*j+1)*DD + d] = h1;
            g_ap[(cb*NN + 2*j  )*DD + d] = a0;
            g_ap[(cb*NN + 2*j+1)*DD + d] = a1;
        }
    } else {
        float h[NN];
#pragma unroll
        for (int n = 0; n < NN; n++) h[n] = 0.f;
        for (int s = 0; s < 32; s++) {
            float4 dr = *(const float4*)&Btr[(sbase + s)*24 + 16];
            float sv = bsv + dr.x*w4.x + dr.y*w4.y + dr.z*w4.z + dr.w*w4.w;
            float dt = softplus_f(sv);
            dtdst[s*DD] = dt;
            float x = xsT[(sbase + s)*132 + d];
            float u = dt*x;
            S += dt;
            const float* bb = &Btr[(sbase + s)*24];
#pragma unroll
            for (int n = 0; n < NN; n++) h[n] = h[n]*__expf(dt*a[n]) + u*bb[n];
        }
#pragma unroll
        for (int n = 0; n < NN; n++) {
            g_hend[(cb*NN + n)*DD + d] = h[n];
            g_ap[(cb*NN + n)*DD + d] = __expf(a[n]*S);
        }
    }
}

// ---------------- K7: scan phase B (cross-chunk prefix, MLP=8) ---------------
__global__ void __launch_bounds__(128) k_scanB()
{
    int bk = blockIdx.x >> 4;
    int n  = blockIdx.x & 15;
    int d = threadIdx.x;
    const int stride = NN*DD;
    int base = ((bk*NCHA)*NN + n)*DD + d;
    float Hv = 0.f;
    for (int c0 = 0; c0 < NCHA; c0 += 8) {
        float ap[8], he[8];
#pragma unroll
        for (int j = 0; j < 8; j++) {
            ap[j] = g_ap[base + (c0+j)*stride];
            he[j] = g_hend[base + (c0+j)*stride];
        }
#pragma unroll
        for (int j = 0; j < 8; j++) {
            g_H0[base + (c0+j)*stride] = Hv;
            Hv = Hv*ap[j] + he[j];
        }
    }
}

// ---------------- K8: scan phase C (rescan + y + scatter, packed f32x2) ------
__global__ void __launch_bounds__(128) k_scanC(const float* Alogs, const float* Ds)
{
    __shared__ float smBC[CHL*32];
    int bk = blockIdx.x >> 6;
    int ch = blockIdx.x & 63;
    int k = bk & 3;
    int b = bk >> 2;
    int d = threadIdx.x;
    int base = ch*CHL;
    {
        const float4* src4 = (const float4*)&g_BC[(bk*LLEN + base)*32];
        float4* dst4 = (float4*)smBC;
        for (int i = d; i < CHL*8; i += 128) dst4[i] = src4[i];
    }
    float a[NN];
    bool fast = true;
#pragma unroll
    for (int n = 0; n < NN; n++) {
        a[n] = -__expf(Alogs[(k*DD + d)*NN + n]);
        fast = fast && (fabsf(a[n] + (float)(n+1)) < 1e-3f);
    }
    int cb = bk*NCHA + ch*2;     // even sub-chunk's H0; rescan covers both
    float Dv = Ds[k*DD + d];
    const float* dtp = &g_dtb[(bk*LLEN + base)*DD + d];
    int xrow = (b*2 + (k & 1))*LLEN;
    bool flip = (k >= 2);
    const float* xp;
    int xstep;
    if (!flip) { xp = &g_xsb[(xrow + base)*DD + d]; xstep = DD; }
    else       { xp = &g_xsb[(xrow + (LLEN-1-base))*DD + d]; xstep = -DD; }
    float* dst = &g_ysb[k*BKLD + b*LLEN*DD];
    __syncthreads();
    if (fast) {
        u64 h2[8];
#pragma unroll
        for (int j = 0; j < 8; j++)
            h2[j] = pk2(g_H0[(cb*NN + 2*j)*DD + d], g_H0[(cb*NN + 2*j+1)*DD + d]);
        float dt_n = dtp[0], x_n = xp[0];
#pragma unroll 2
        for (int s = 0; s < CHL; s++) {
            float dt = dt_n, x = x_n;
            if (s + 1 < CHL) { dt_n = dtp[(s+1)*DD]; x_n = xp[(s+1)*xstep]; }
            float u = dt*x;
            u64 u2 = pk2(u, u);
            float r = __expf(-dt);
            u64 p2[8];
            pow_tree2(r, p2);
            const ulonglong2* bc2 = (const ulonglong2*)&smBC[s*32];
            u64 ya = 0ull, yb = 0ull;
#pragma unroll
            for (int j = 0; j < 4; j++) {
                ulonglong2 bp = bc2[j];
                ulonglong2 cp = bc2[4 + j];
                h2[2*j]   = fma2(h2[2*j],   p2[2*j],   mul2(u2, bp.x));
                ya = fma2(h2[2*j], cp.x, ya);
                h2[2*j+1] = fma2(h2[2*j+1], p2[2*j+1], mul2(u2, bp.y));
                yb = fma2(h2[2*j+1], cp.y, yb);
            }
            float y0, y1, y2, y3;
            upk2(ya, y0, y1);
            upk2(yb, y2, y3);
            float ys = (y0 + y1) + (y2 + y3) + x*Dv;
            int sa = base + s;
            int lrow;
            if (k == 0)      lrow = sa;
            else if (k == 1) lrow = ((sa & 63) << 6) | (sa >> 6);
            else if (k == 2) lrow = LLEN - 1 - sa;
            else { int m = LLEN - 1 - sa; lrow = ((m & 63) << 6) | (m >> 6); }
            dst[lrow*DD + d] = ys;
        }
    } else {
        float h[NN];
#pragma unroll
        for (int n = 0; n < NN; n++) h[n] = g_H0[(cb*NN + n)*DD + d];
        for (int s = 0; s < CHL; s++) {
            float dt = dtp[s*DD];
            float x  = xp[s*xstep];
            float u = dt*x;
            const float* bb = &smBC[s*32];
            const float* cc = &smBC[s*32 + 16];
            float y0 = 0.f, y1 = 0.f, y2 = 0.f, y3 = 0.f;
#pragma unroll
            for (int n = 0; n < NN; n += 4) {
                h[n+0] = h[n+0]*__expf(dt*a[n+0]) + u*bb[n+0]; y0 += h[n+0]*cc[n+0];
                h[n+1] = h[n+1]*__expf(dt*a[n+1]) + u*bb[n+1]; y1 += h[n+1]*cc[n+1];
                h[n+2] = h[n+2]*__expf(dt*a[n+2]) + u*bb[n+2]; y2 += h[n+2]*cc[n+2];
                h[n+3] = h[n+3]*__expf(dt*a[n+3]) + u*bb[n+3]; y3 += h[n+3]*cc[n+3];
            }
            float ys = (y0 + y1) + (y2 + y3) + x*Dv;
            int sa = base + s;
            int lrow;
            if (k == 0)      lrow = sa;
            else if (k == 1) lrow = ((sa & 63) << 6) | (sa >> 6);
            else if (k == 2) lrow = LLEN - 1 - sa;
            else { int m = LLEN - 1 - sa; lrow = ((m & 63) << 6) | (m >> 6); }
            dst[lrow*DD + d] = ys;
        }
    }
}

// ---------------- K9: combine + LN + gates + out-proj + residual -------------
__global__ void __launch_bounds__(256) k_final(const float* inp, const float* lnw,
                                               const float* lnb, const float* Wout,
                                               float* out)
{
    __shared__ float Wsm[64*132];
    __shared__ float val_sm[8*128];
    __shared__ float osm[64*8];
    int t = threadIdx.x;
    int b = blockIdx.x >> 7;
    int lbase = (blockIdx.x & 127) * 32;
    for (int i = t; i < 64*32; i += 256) {
        int c = i >> 5, q = i & 31;
        *(float4*)&Wsm[c*132 + q*4] = ((const float4*)Wout)[i];
    }
    __syncthreads();
    int w = t >> 5, lane = t & 31;
    float4 lw = ((const float4*)lnw)[lane];
    float4 lb = ((const float4*)lnb)[lane];
    float4 cd = *(const float4*)&g_cond[b*DD + lane*4];
    for (int it = 0; it < 4; it++) {
        int l0 = lbase + it*8;
        int l = l0 + w;
        int off = (b*LLEN + l)*DD + lane*4;
        float4 y4;
        {
            float4 a0 = *(const float4*)&g_ysb[0*BKLD + off];
            float4 a1 = *(const float4*)&g_ysb[1*BKLD + off];
            float4 a2 = *(const float4*)&g_ysb[2*BKLD + off];
            float4 a3 = *(const float4*)&g_ysb[3*BKLD + off];
            y4.x = a0.x + a1.x + a2.x + a3.x;
            y4.y = a0.y + a1.y + a2.y + a3.y;
            y4.z = a0.z + a1.z + a2.z + a3.z;
            y4.w = a0.w + a1.w + a2.w + a3.w;
        }
        float s1 = y4.x + y4.y + y4.z + y4.w;
        float s2 = y4.x*y4.x + y4.y*y4.y + y4.z*y4.z + y4.w*y4.w;
        for (int o2 = 16; o2; o2 >>= 1) {
            s1 += __shfl_xor_sync(0xffffffffu, s1, o2);
            s2 += __shfl_xor_sync(0xffffffffu, s2, o2);
        }
        float mean = s1 * (1.f/128.f);
        float var  = s2 * (1.f/128.f) - mean*mean;
        float rstd = rsqrtf(var + EPSV);
        float4 z4 = *(const float4*)&g_zs[off];
        float4 v4;
        v4.x = ((y4.x - mean)*rstd*lw.x + lb.x) * cd.x * z4.x;
        v4.y = ((y4.y - mean)*rstd*lw.y + lb.y) * cd.y * z4.y;
        v4.z = ((y4.z - mean)*rstd*lw.z + lb.z) * cd.z * z4.z;
        v4.w = ((y4.w - mean)*rstd*lw.w + lb.w) * cd.w * z4.w;
        *(float4*)&val_sm[w*128 + lane*4] = v4;
        __syncwarp();
        float acc0 = 0.f, acc1 = 0.f;
        const float4* vp = (const float4*)&val_sm[w*128];
        const float4* w0 = (const float4*)&Wsm[lane*132];
        const float4* w1 = (const float4*)&Wsm[(lane+32)*132];
#pragma unroll 8
        for (int q = 0; q < 32; q++) {
            float4 v = vp[q];
            float4 wa = w0[q];
            float4 wb = w1[q];
            acc0 += v.x*wa.x + v.y*wa.y + v.z*wa.z + v.w*wa.w;
            acc1 += v.x*wb.x + v.y*wb.y + v.z*wb.z + v.w*wb.w;
        }
        osm[lane*8 + w] = acc0;
        osm[(lane+32)*8 + w] = acc1;
        __syncthreads();
        for (int i = t; i < 64*8; i += 256) {
            int c = i >> 3, li = i & 7;
            int gi = (b*CC + c)*LLEN + l0 + li;
            out[gi] = osm[c*8 + li] + inp[gi]*g_att[b*CC + c];
        }
        __syncthreads();
    }
}

extern "C" void kernel_launch(void* const* d_in, const int* in_sizes, int n_in,
                              void* d_out, int out_size)
{
    const float* inp   = (const float*)d_in[0];
    const float* rep   = (const float*)d_in[1];
    const float* Wg    = (const float*)d_in[2];
    const float* bg    = (const float*)d_in[3];
    const float* Wb    = (const float*)d_in[4];
    const float* bbp   = (const float*)d_in[5];
    const float* Win   = (const float*)d_in[6];
    const float* cw    = (const float*)d_in[7];
    const float* cb    = (const float*)d_in[8];
    const float* xpw   = (const float*)d_in[9];
    const float* dtw   = (const float*)d_in[10];
    const float* dtbp  = (const float*)d_in[11];
    const float* Alogs = (const float*)d_in[12];
    const float* Ds    = (const float*)d_in[13];
    const float* lnw   = (const float*)d_in[14];
    const float* lnb   = (const float*)d_in[15];
    const float* Wc    = (const float*)d_in[16];
    const float* bc    = (const float*)d_in[17];
    const float* Wout  = (const float*)d_in[18];
    const float* Wf1   = (const float*)d_in[19];
    const float* bf1   = (const float*)d_in[20];
    const float* Wf2   = (const float*)d_in[21];
    const float* bf2   = (const float*)d_in[22];
    float* out = (float*)d_out;

    cudaFuncSetAttribute(k_xdbl, cudaFuncAttributeMaxDynamicSharedMemorySize,
                         XDBL_SMEM * (int)sizeof(float));

    k_small<<<1 + BB*CC, 256>>>(rep, Wg, bg, Wb, bbp, Wc, bc, Wf1, bf1, Wf2, bf2, Win, inp);
    k_inproj<<<BB*128, 256>>>(inp);
    k_conv<<<BB*DD, 256>>>(cw, cb);
    k_xdbl<<<BB*KK*64, 256, XDBL_SMEM * (int)sizeof(float)>>>(xpw, dtw, dtbp, Alogs);
    k_scanB<<<BB*KK*NN, 128>>>();
    k_scanC<<<BB*KK*64, 128>>>(Alogs, Ds);
    k_final<<<BB*128, 256>>>(inp, lnw, lnb, Wout, out);
}

// round 12
// speedup vs baseline: 1.0625x; 1.0217x over previous
#include <cuda_runtime.h>
#include <math.h>

#define BB 4
#define CC 64
#define HH 64
#define WW 64
#define LLEN 4096
#define RR 64
#define DD 128
#define KK 4
#define NN 16
#define NCHA 128              // phase-A sub-chunks per (b,k), 32 steps each
#define CHL 64                // scanC chunk length (2 sub-chunks)
#define EPSV 1e-5f
#define BKLD (BB*LLEN*DD)
// smem: xsT [64][132] + Wp[36][128] (reused as xdbl[36][68] + Btr[64][24])
#define XDBL_SMEM (64*132 + 36*128)

typedef unsigned long long u64;
typedef unsigned int u32;

__device__ __forceinline__ u64 pk2(float lo, float hi) {
    u64 r; u32 a = __float_as_uint(lo), b = __float_as_uint(hi);
    asm("mov.b64 %0, {%1, %2};" : "=l"(r) : "r"(a), "r"(b));
    return r;
}
__device__ __forceinline__ u64 fma2(u64 a, u64 b, u64 c) {
    u64 d; asm("fma.rn.f32x2 %0, %1, %2, %3;" : "=l"(d) : "l"(a), "l"(b), "l"(c));
    return d;
}
__device__ __forceinline__ u64 mul2(u64 a, u64 b) {
    u64 d; asm("mul.rn.f32x2 %0, %1, %2;" : "=l"(d) : "l"(a), "l"(b));
    return d;
}
__device__ __forceinline__ void upk2(u64 v, float& lo, float& hi) {
    u32 a, b; asm("mov.b64 {%0, %1}, %2;" : "=r"(a), "=r"(b) : "l"(v));
    lo = __uint_as_float(a); hi = __uint_as_float(b);
}
// p2[j] = {r^(2j+1), r^(2j+2)}, dependency depth ~4
__device__ __forceinline__ void pow_tree2(float r, u64* p2) {
    float r2 = r*r, r4 = r2*r2, r8 = r4*r4;
    u64 q0 = pk2(r, r2), s2 = pk2(r2, r2), s4 = pk2(r4, r4), s8 = pk2(r8, r8);
    p2[0] = q0;
    p2[1] = mul2(q0, s2);
    p2[2] = mul2(q0, s4);
    p2[3] = mul2(p2[1], s4);
    p2[4] = mul2(q0, s8);
    p2[5] = mul2(p2[1], s8);
    p2[6] = mul2(p2[2], s8);
    p2[7] = mul2(p2[3], s8);
}
// fast softplus: branch-light, MUFU-based
__device__ __forceinline__ float softplus_f(float s) {
    float as = fabsf(s);
    float sp = fmaxf(s, 0.f) + __logf(1.f + __expf(-as));
    return (s > 20.f) ? s : sp;
}

// ---------------- scratch ----------------
__device__ float g_gamma[BB*CC];
__device__ float g_beta[BB*CC];
__device__ float g_cond[BB*DD];
__device__ float g_att[BB*CC];
__device__ float g_mu[BB*CC];
__device__ float g_rstd[BB*CC];
__device__ float g_WinT[CC*2*DD];
__device__ float g_xc[BB*DD*LLEN];
__device__ float g_zs[BB*LLEN*DD];
__device__ float g_xa[BB*DD*LLEN];
__device__ float g_xaT[BB*DD*LLEN];
__device__ float g_xsb[BB*2*LLEN*DD];      // only k=0,1 stored; k>=2 is a flip
__device__ float g_BC[BB*KK*LLEN*36];      // [B(16)|C(16)|dt-rank(4)] per (bk,l)
__device__ float g_hend[BB*KK*NCHA*NN*DD];
__device__ float g_S[BB*KK*NCHA*DD];       // per-sub-chunk dt-sum
__device__ float g_H0[BB*KK*NCHA*NN*DD];
__device__ float g_ysb[KK*BB*LLEN*DD];

// ---------------- K1: small GEMVs + W_in transpose + IN stats ----------------
__global__ void k_small(const float* rep, const float* Wg, const float* bg,
                        const float* Wb, const float* bb,
                        const float* Wc, const float* bc,
                        const float* Wf1, const float* bf1,
                        const float* Wf2, const float* bf2,
                        const float* Win, const float* inp)
{
    if (blockIdx.x > 0) {       // instance-norm stats, one block per (b,c)
        int bc_i = blockIdx.x - 1;
        int t = threadIdx.x;
        const float* p = inp + bc_i*LLEN;
        float s = 0.f, s2 = 0.f;
        for (int i = t; i < LLEN; i += 256) { float v = p[i]; s += v; s2 += v*v; }
        __shared__ float sh[64];
        for (int off = 16; off; off >>= 1) {
            s  += __shfl_xor_sync(0xffffffffu, s,  off);
            s2 += __shfl_xor_sync(0xffffffffu, s2, off);
        }
        int w = t >> 5, lane = t & 31;
        if (lane == 0) { sh[w] = s; sh[32 + w] = s2; }
        __syncthreads();
        if (t == 0) {
            float S = 0.f, S2 = 0.f;
            for (int i = 0; i < 8; i++) { S += sh[i]; S2 += sh[32 + i]; }
            float mu = S / (float)LLEN;
            float var = S2 / (float)LLEN - mu*mu;
            g_mu[bc_i] = mu;
            g_rstd[bc_i] = rsqrtf(var + EPSV);
        }
        return;
    }
    __shared__ float rs[BB*RR];
    __shared__ float a_sm[BB*16];
    int t = threadIdx.x;
    if (t < BB*RR) rs[t] = rep[t];
    __syncthreads();
    {
        int b = t >> 6, c = t & 63;
        float ag = 0.f, ab = 0.f;
        for (int r = 0; r < RR; r++) {
            float rv = rs[b*RR + r];
            ag += rv * Wg[c*RR + r];
            ab += rv * Wb[c*RR + r];
        }
        g_gamma[t] = ag + bg[c];
        g_beta[t]  = ab + bb[c];
    }
    for (int i = t; i < BB*DD; i += 256) {
        int b = i >> 7, d = i & 127;
        float a = 0.f;
        for (int r = 0; r < RR; r++) a += rs[b*RR + r] * Wc[d*RR + r];
        g_cond[i] = 1.0f + a + bc[d];
    }
    if (t < BB*16) {
        int b = t >> 4, j = t & 15;
        float a = 0.f;
        for (int r = 0; r < RR; r++) a += rs[b*RR + r] * Wf1[j*RR + r];
        a += bf1[j];
        a_sm[t] = a > 0.f ? a : 0.f;
    }
    __syncthreads();
    {
        int b = t >> 6, c = t & 63;
        float s = bf2[c];
        for (int j = 0; j < 16; j++) s += a_sm[b*16 + j] * Wf2[c*16 + j];
        g_att[t] = 1.0f / (1.0f + __expf(-s));
    }
    for (int i = t; i < 2*DD*CC; i += 256) {
        int o = i / CC, c = i - o*CC;
        g_WinT[c*(2*DD) + o] = Win[i];
    }
}

// ---------------- K3: FiLM + in-projection GEMM ----------------
__global__ void __launch_bounds__(256) k_inproj(const float* inp)
{
    __shared__ float buf[256*33];
    int bx = blockIdx.x;
    int b  = bx >> 7;
    int l0 = (bx & 127) * 32;
    int t = threadIdx.x;
    for (int i = t; i < CC*32; i += 256) {
        int c = i >> 5, li = i & 31;
        int bc = b*CC + c;
        float v  = inp[bc*LLEN + l0 + li];
        float sc = g_rstd[bc] * (1.0f + g_gamma[bc]);
        float bi = g_beta[bc] - g_mu[bc]*sc;
        buf[c*36 + li] = v*sc + bi;
    }
    __syncthreads();
    int o = t;
    float acc[32];
#pragma unroll
    for (int li = 0; li < 32; li++) acc[li] = 0.f;
    for (int c = 0; c < CC; c++) {
        float w = g_WinT[c*256 + o];
        const float4* xp = (const float4*)&buf[c*36];
#pragma unroll
        for (int q = 0; q < 8; q++) {
            float4 x4 = xp[q];
            acc[q*4+0] += w*x4.x; acc[q*4+1] += w*x4.y;
            acc[q*4+2] += w*x4.z; acc[q*4+3] += w*x4.w;
        }
    }
    if (o >= DD) {
#pragma unroll
        for (int li = 0; li < 32; li++) {
            float z = acc[li];
            acc[li] = z / (1.0f + __expf(-z));
        }
    }
    __syncthreads();
#pragma unroll
    for (int li = 0; li < 32; li++) buf[o*33 + li] = acc[li];
    __syncthreads();
    for (int i = t; i < DD*32; i += 256) {
        int d = i >> 5, li = i & 31;
        g_xc[(b*DD + d)*LLEN + l0 + li] = buf[d*33 + li];
    }
    for (int i = t; i < DD*32; i += 256) {
        int li = i >> 7, zd = i & 127;
        g_zs[(b*LLEN + l0 + li)*DD + zd] = buf[(128 + zd)*33 + li];
    }
}

// ---------------- K4: depthwise 3x3 conv + silu (+ transpose) ----------------
__global__ void __launch_bounds__(256) k_conv(const float* cw, const float* cb)
{
    int bd = blockIdx.x;
    int d = bd & 127;
    __shared__ float insm[66*66];
    __shared__ float osm[64*65];
    int t = threadIdx.x;
    if (t < 66) { insm[t] = 0.f; insm[65*66 + t] = 0.f; }
    if (t < 64) { insm[(t+1)*66] = 0.f; insm[(t+1)*66 + 65] = 0.f; }
    const float* src = &g_xc[bd*LLEN];
    for (int i = t; i < LLEN; i += 256) {
        int h = i >> 6, w = i & 63;
        insm[(h+1)*66 + (w+1)] = src[i];
    }
    float wv[9];
#pragma unroll
    for (int i = 0; i < 9; i++) wv[i] = cw[d*9 + i];
    float bias = cb[d];
    __syncthreads();
    float* dsta = &g_xa[bd*LLEN];
    for (int i = t; i < LLEN; i += 256) {
        int h = i >> 6, w = i & 63;
        float a = bias;
#pragma unroll
        for (int ki = 0; ki < 3; ki++)
#pragma unroll
            for (int kj = 0; kj < 3; kj++)
                a += insm[(h+ki)*66 + (w+kj)] * wv[ki*3+kj];
        float v = a / (1.0f + __expf(-a));
        dsta[i] = v;
        osm[h*65 + w] = v;
    }
    __syncthreads();
    float* dstt = &g_xaT[bd*LLEN];
    for (int i = t; i < LLEN; i += 256) {
        int h = i & 63, w = i >> 6;
        dstt[i] = osm[h*65 + w];
    }
}

// ---- K5: x_dbl GEMM (smem weights) + dt-proj + fused phase-A scan -----------
// 256 threads: GEMM g=t>>6 (9 rows) x li=t&63; scan 2 sub-chunks of 32 steps.
__global__ void __launch_bounds__(256, 4) k_xdbl(const float* xpw, const float* dtw,
                                                 const float* dtbp, const float* Alogs)
{
    extern __shared__ float dsm[];
    float* xsT  = dsm;                    // [64][132], live through the scan
    float* Wp   = dsm + 64*132;           // [36][128]; dead after GEMM -> reused:
    float* xdbl = Wp;                     //   [36][68]  (2448 floats)
    float* Btr  = Wp + 2448;              //   [64][24]: 0-15 = B, 16-19 = dt-rank
    int bx = blockIdx.x;                  // 1024 blocks
    int b  = bx >> 8;
    int k  = (bx >> 6) & 3;
    int lt = bx & 63;
    int bk = b*KK + k;
    int l0 = lt*64;
    int t = threadIdx.x;
    {   // float4 weight staging into smem
        const float4* wsrc = (const float4*)(xpw + k*36*128);
        float4* wdst = (float4*)Wp;
        for (int i = t; i < 36*32; i += 256) wdst[i] = wsrc[i];
    }
    const float* src = (k & 1) ? &g_xaT[b*DD*LLEN] : &g_xa[b*DD*LLEN];
    bool flip = (k >= 2);
    for (int i = t; i < DD*64; i += 256) {        // coalesced over l
        int d = i >> 6, li = i & 63;
        int l = l0 + li;
        int m = flip ? (LLEN - 1 - l) : l;
        xsT[li*132 + d] = src[d*LLEN + m];
    }
    __syncthreads();
    if (k < 2) {
        int bk2 = b*2 + k;
        for (int i = t; i < DD*64; i += 256) {
            int li = i >> 7, d = i & 127;
            g_xsb[(bk2*LLEN + l0 + li)*DD + d] = xsT[li*132 + d];
        }
    }
    // GEMM: g = row group (9 rows), li = single l column, weights via smem broadcast
    int g = t >> 6, li = t & 63;
    float acc[9];
    {
#pragma unroll
        for (int r = 0; r < 9; r++) acc[r] = 0.f;
        const float4* xp = (const float4*)&xsT[li*132];
        const float4* wb = (const float4*)&Wp[g*9*128];
#pragma unroll 4
        for (int d4 = 0; d4 < 32; d4++) {
            float4 x4 = xp[d4];
#pragma unroll
            for (int r = 0; r < 9; r++) {
                float4 w4 = wb[r*32 + d4];
                acc[r] += x4.x*w4.x + x4.y*w4.y + x4.z*w4.z + x4.w*w4.w;
            }
        }
    }
    __syncthreads();          // all Wp reads done; safe to overwrite with xdbl
#pragma unroll
    for (int r = 0; r < 9; r++) xdbl[(g*9 + r)*68 + li] = acc[r];
    __syncthreads();
    // Btr build + g_BC write (36 cols: B | C | dt-rank)
    for (int i = t; i < 16*64; i += 256) {        // B rows -> Btr
        int n = i >> 6, li2 = i & 63;
        Btr[li2*24 + n] = xdbl[(4 + n)*68 + li2];
    }
    for (int i = t; i < 4*64; i += 256) {         // dt-rank rows -> Btr
        int r = i >> 6, li2 = i & 63;
        Btr[li2*24 + 16 + r] = xdbl[r*68 + li2];
    }
    for (int i = t; i < 64*36; i += 256) {        // B|C|dtr -> (bk,l,36) for scanC
        int li2 = i / 36, j = i - li2*36;
        int srow = (j < 32) ? (4 + j) : (j - 32);
        g_BC[(bk*LLEN + l0 + li2)*36 + j] = xdbl[srow*68 + li2];
    }
    __syncthreads();
    // ---- fused phase-A scan: 2 sub-chunks of 32 steps ----
    int sub = t >> 7;
    int d = t & 127;
    float a[NN];
    bool fast = true;
#pragma unroll
    for (int n = 0; n < NN; n++) {
        a[n] = -__expf(Alogs[(k*DD + d)*NN + n]);
        fast = fast && (fabsf(a[n] + (float)(n+1)) < 1e-3f);
    }
    float4 w4 = *(const float4*)&dtw[(k*DD + d)*4];
    float bsv = dtbp[k*DD + d];
    int sbase = sub*32;
    float S = 0.f;
    int cb = bk*NCHA + lt*2 + sub;
    if (fast) {
        u64 h2[8];
#pragma unroll
        for (int j = 0; j < 8; j++) h2[j] = 0ull;
#pragma unroll 2
        for (int s = 0; s < 32; s++) {
            float4 dr = *(const float4*)&Btr[(sbase + s)*24 + 16];
            float sv = bsv + dr.x*w4.x + dr.y*w4.y + dr.z*w4.z + dr.w*w4.w;
            float dt = softplus_f(sv);
            float x = xsT[(sbase + s)*132 + d];
            float u = dt*x;
            S += dt;
            u64 u2 = pk2(u, u);
            float r = __expf(-dt);
            u64 p2[8];
            pow_tree2(r, p2);
            const ulonglong2* bc2 = (const ulonglong2*)&Btr[(sbase + s)*24];
#pragma unroll
            for (int j = 0; j < 4; j++) {
                ulonglong2 bp = bc2[j];
                h2[2*j]   = fma2(h2[2*j],   p2[2*j],   mul2(u2, bp.x));
                h2[2*j+1] = fma2(h2[2*j+1], p2[2*j+1], mul2(u2, bp.y));
            }
        }
#pragma unroll
        for (int j = 0; j < 8; j++) {
            float h0, h1;
            upk2(h2[j], h0, h1);
            g_hend[(cb*NN + 2*j  )*DD + d] = h0;
            g_hend[(cb*NN + 2*j+1)*DD + d] = h1;
        }
        g_S[cb*DD + d] = S;
    } else {
        float h[NN];
#pragma unroll
        for (int n = 0; n < NN; n++) h[n] = 0.f;
        for (int s = 0; s < 32; s++) {
            float4 dr = *(const float4*)&Btr[(sbase + s)*24 + 16];
            float sv = bsv + dr.x*w4.x + dr.y*w4.y + dr.z*w4.z + dr.w*w4.w;
            float dt = softplus_f(sv);
            float x = xsT[(sbase + s)*132 + d];
            float u = dt*x;
            S += dt;
            const float* bb = &Btr[(sbase + s)*24];
#pragma unroll
            for (int n = 0; n < NN; n++) h[n] = h[n]*__expf(dt*a[n]) + u*bb[n];
        }
#pragma unroll
        for (int n = 0; n < NN; n++) {
            g_hend[(cb*NN + n)*DD + d] = h[n];
        }
        g_S[cb*DD + d] = S;
    }
}

// ------- K7: scan phase B (cross-chunk prefix; ap recomputed from S) ---------
__global__ void __launch_bounds__(128) k_scanB(const float* Alogs)
{
    int bk = blockIdx.x >> 4;
    int n  = blockIdx.x & 15;
    int k  = bk & 3;
    int d = threadIdx.x;
    const int stride = NN*DD;
    int base = ((bk*NCHA)*NN + n)*DD + d;
    int sbase = bk*NCHA*DD + d;
    float a = -__expf(Alogs[(k*DD + d)*NN + n]);
    float Hv = 0.f;
    for (int c0 = 0; c0 < NCHA; c0 += 8) {
        float Sv[8], he[8];
#pragma unroll
        for (int j = 0; j < 8; j++) {
            Sv[j] = g_S[sbase + (c0+j)*DD];
            he[j] = g_hend[base + (c0+j)*stride];
        }
        float ap[8];
#pragma unroll
        for (int j = 0; j < 8; j++) ap[j] = __expf(a*Sv[j]);
#pragma unroll
        for (int j = 0; j < 8; j++) {
            g_H0[base + (c0+j)*stride] = Hv;
            Hv = Hv*ap[j] + he[j];
        }
    }
}

// -------- K8: scan phase C (rescan + y + scatter; dt recomputed) -------------
__global__ void __launch_bounds__(128) k_scanC(const float* Alogs, const float* Ds,
                                               const float* dtw, const float* dtbp)
{
    __shared__ float smBC[CHL*36];
    int bk = blockIdx.x >> 6;
    int ch = blockIdx.x & 63;
    int k = bk & 3;
    int b = bk >> 2;
    int d = threadIdx.x;
    int base = ch*CHL;
    {
        const float4* src4 = (const float4*)&g_BC[(bk*LLEN + base)*36];
        float4* dst4 = (float4*)smBC;
        for (int i = d; i < CHL*9; i += 128) dst4[i] = src4[i];
    }
    float a[NN];
    bool fast = true;
#pragma unroll
    for (int n = 0; n < NN; n++) {
        a[n] = -__expf(Alogs[(k*DD + d)*NN + n]);
        fast = fast && (fabsf(a[n] + (float)(n+1)) < 1e-3f);
    }
    int cb = bk*NCHA + ch*2;     // even sub-chunk's H0; rescan covers both
    float Dv = Ds[k*DD + d];
    float4 w4 = *(const float4*)&dtw[(k*DD + d)*4];
    float bsv = dtbp[k*DD + d];
    int xrow = (b*2 + (k & 1))*LLEN;
    bool flip = (k >= 2);
    const float* xp;
    int xstep;
    if (!flip) { xp = &g_xsb[(xrow + base)*DD + d]; xstep = DD; }
    else       { xp = &g_xsb[(xrow + (LLEN-1-base))*DD + d]; xstep = -DD; }
    float* dst = &g_ysb[k*BKLD + b*LLEN*DD];
    __syncthreads();
    if (fast) {
        u64 h2[8];
#pragma unroll
        for (int j = 0; j < 8; j++)
            h2[j] = pk2(g_H0[(cb*NN + 2*j)*DD + d], g_H0[(cb*NN + 2*j+1)*DD + d]);
        float x_n = xp[0];
#pragma unroll 2
        for (int s = 0; s < CHL; s++) {
            float x = x_n;
            if (s + 1 < CHL) x_n = xp[(s+1)*xstep];
            float4 dr = *(const float4*)&smBC[s*36 + 32];
            float sv = bsv + dr.x*w4.x + dr.y*w4.y + dr.z*w4.z + dr.w*w4.w;
            float dt = softplus_f(sv);
            float u = dt*x;
            u64 u2 = pk2(u, u);
            float r = __expf(-dt);
            u64 p2[8];
            pow_tree2(r, p2);
            const ulonglong2* bc2 = (const ulonglong2*)&smBC[s*36];
            u64 ya = 0ull, yb = 0ull;
#pragma unroll
            for (int j = 0; j < 4; j++) {
                ulonglong2 bp = bc2[j];
                ulonglong2 cp = bc2[4 + j];
                h2[2*j]   = fma2(h2[2*j],   p2[2*j],   mul2(u2, bp.x));
                ya = fma2(h2[2*j], cp.x, ya);
                h2[2*j+1] = fma2(h2[2*j+1], p2[2*j+1], mul2(u2, bp.y));
                yb = fma2(h2[2*j+1], cp.y, yb);
            }
            float y0, y1, y2, y3;
            upk2(ya, y0, y1);
            upk2(yb, y2, y3);
            float ys = (y0 + y1) + (y2 + y3) + x*Dv;
            int sa = base + s;
            int lrow;
            if (k == 0)      lrow = sa;
            else if (k == 1) lrow = ((sa & 63) << 6) | (sa >> 6);
            else if (k == 2) lrow = LLEN - 1 - sa;
            else { int m = LLEN - 1 - sa; lrow = ((m & 63) << 6) | (m >> 6); }
            dst[lrow*DD + d] = ys;
        }
    } else {
        float h[NN];
#pragma unroll
        for (int n = 0; n < NN; n++) h[n] = g_H0[(cb*NN + n)*DD + d];
        for (int s = 0; s < CHL; s++) {
            float x  = xp[s*xstep];
            float4 dr = *(const float4*)&smBC[s*36 + 32];
            float sv = bsv + dr.x*w4.x + dr.y*w4.y + dr.z*w4.z + dr.w*w4.w;
            float dt = softplus_f(sv);
            float u = dt*x;
            const float* bb = &smBC[s*36];
            const float* cc = &smBC[s*36 + 16];
            float y0 = 0.f, y1 = 0.f, y2 = 0.f, y3 = 0.f;
#pragma unroll
            for (int n = 0; n < NN; n += 4) {
                h[n+0] = h[n+0]*__expf(dt*a[n+0]) + u*bb[n+0]; y0 += h[n+0]*cc[n+0];
                h[n+1] = h[n+1]*__expf(dt*a[n+1]) + u*bb[n+1]; y1 += h[n+1]*cc[n+1];
                h[n+2] = h[n+2]*__expf(dt*a[n+2]) + u*bb[n+2]; y2 += h[n+2]*cc[n+2];
                h[n+3] = h[n+3]*__expf(dt*a[n+3]) + u*bb[n+3]; y3 += h[n+3]*cc[n+3];
            }
            float ys = (y0 + y1) + (y2 + y3) + x*Dv;
            int sa = base + s;
            int lrow;
            if (k == 0)      lrow = sa;
            else if (k == 1) lrow = ((sa & 63) << 6) | (sa >> 6);
            else if (k == 2) lrow = LLEN - 1 - sa;
            else { int m = LLEN - 1 - sa; lrow = ((m & 63) << 6) | (m >> 6); }
            dst[lrow*DD + d] = ys;
        }
    }
}

// ---------------- K9: combine + LN + gates + out-proj + residual -------------
__global__ void __launch_bounds__(256) k_final(const float* inp, const float* lnw,
                                               const float* lnb, const float* Wout,
                                               float* out)
{
    __shared__ float Wsm[64*132];
    __shared__ float val_sm[8*128];
    __shared__ float osm[64*8];
    int t = threadIdx.x;
    int b = blockIdx.x >> 7;
    int lbase = (blockIdx.x & 127) * 32;
    for (int i = t; i < 64*32; i += 256) {
        int c = i >> 5, q = i & 31;
        *(float4*)&Wsm[c*132 + q*4] = ((const float4*)Wout)[i];
    }
    __syncthreads();
    int w = t >> 5, lane = t & 31;
    float4 lw = ((const float4*)lnw)[lane];
    float4 lb = ((const float4*)lnb)[lane];
    float4 cd = *(const float4*)&g_cond[b*DD + lane*4];
    for (int it = 0; it < 4; it++) {
        int l0 = lbase + it*8;
        int l = l0 + w;
        int off = (b*LLEN + l)*DD + lane*4;
        float4 y4;
        {
            float4 a0 = *(const float4*)&g_ysb[0*BKLD + off];
            float4 a1 = *(const float4*)&g_ysb[1*BKLD + off];
            float4 a2 = *(const float4*)&g_ysb[2*BKLD + off];
            float4 a3 = *(const float4*)&g_ysb[3*BKLD + off];
            y4.x = a0.x + a1.x + a2.x + a3.x;
            y4.y = a0.y + a1.y + a2.y + a3.y;
            y4.z = a0.z + a1.z + a2.z + a3.z;
            y4.w = a0.w + a1.w + a2.w + a3.w;
        }
        float s1 = y4.x + y4.y + y4.z + y4.w;
        float s2 = y4.x*y4.x + y4.y*y4.y + y4.z*y4.z + y4.w*y4.w;
        for (int o2 = 16; o2; o2 >>= 1) {
            s1 += __shfl_xor_sync(0xffffffffu, s1, o2);
            s2 += __shfl_xor_sync(0xffffffffu, s2, o2);
        }
        float mean = s1 * (1.f/128.f);
        float var  = s2 * (1.f/128.f) - mean*mean;
        float rstd = rsqrtf(var + EPSV);
        float4 z4 = *(const float4*)&g_zs[off];
        float4 v4;
        v4.x = ((y4.x - mean)*rstd*lw.x + lb.x) * cd.x * z4.x;
        v4.y = ((y4.y - mean)*rstd*lw.y + lb.y) * cd.y * z4.y;
        v4.z = ((y4.z - mean)*rstd*lw.z + lb.z) * cd.z * z4.z;
        v4.w = ((y4.w - mean)*rstd*lw.w + lb.w) * cd.w * z4.w;
        *(float4*)&val_sm[w*128 + lane*4] = v4;
        __syncwarp();
        float acc0 = 0.f, acc1 = 0.f;
        const float4* vp = (const float4*)&val_sm[w*128];
        const float4* w0 = (const float4*)&Wsm[lane*132];
        const float4* w1 = (const float4*)&Wsm[(lane+32)*132];
#pragma unroll 8
        for (int q = 0; q < 32; q++) {
            float4 v = vp[q];
            float4 wa = w0[q];
            float4 wb = w1[q];
            acc0 += v.x*wa.x + v.y*wa.y + v.z*wa.z + v.w*wa.w;
            acc1 += v.x*wb.x + v.y*wb.y + v.z*wb.z + v.w*wb.w;
        }
        osm[lane*8 + w] = acc0;
        osm[(lane+32)*8 + w] = acc1;
        __syncthreads();
        for (int i = t; i < 64*8; i += 256) {
            int c = i >> 3, li = i & 7;
            int gi = (b*CC + c)*LLEN + l0 + li;
            out[gi] = osm[c*8 + li] + inp[gi]*g_att[b*CC + c];
        }
        __syncthreads();
    }
}

extern "C" void kernel_launch(void* const* d_in, const int* in_sizes, int n_in,
                              void* d_out, int out_size)
{
    const float* inp   = (const float*)d_in[0];
    const float* rep   = (const float*)d_in[1];
    const float* Wg    = (const float*)d_in[2];
    const float* bg    = (const float*)d_in[3];
    const float* Wb    = (const float*)d_in[4];
    const float* bbp   = (const float*)d_in[5];
    const float* Win   = (const float*)d_in[6];
    const float* cw    = (const float*)d_in[7];
    const float* cb    = (const float*)d_in[8];
    const float* xpw   = (const float*)d_in[9];
    const float* dtw   = (const float*)d_in[10];
    const float* dtbp  = (const float*)d_in[11];
    const float* Alogs = (const float*)d_in[12];
    const float* Ds    = (const float*)d_in[13];
    const float* lnw   = (const float*)d_in[14];
    const float* lnb   = (const float*)d_in[15];
    const float* Wc    = (const float*)d_in[16];
    const float* bc    = (const float*)d_in[17];
    const float* Wout  = (const float*)d_in[18];
    const float* Wf1   = (const float*)d_in[19];
    const float* bf1   = (const float*)d_in[20];
    const float* Wf2   = (const float*)d_in[21];
    const float* bf2   = (const float*)d_in[22];
    float* out = (float*)d_out;

    cudaFuncSetAttribute(k_xdbl, cudaFuncAttributeMaxDynamicSharedMemorySize,
                         XDBL_SMEM * (int)sizeof(float));

    k_small<<<1 + BB*CC, 256>>>(rep, Wg, bg, Wb, bbp, Wc, bc, Wf1, bf1, Wf2, bf2, Win, inp);
    k_inproj<<<BB*128, 256>>>(inp);
    k_conv<<<BB*DD, 256>>>(cw, cb);
    k_xdbl<<<BB*KK*64, 256, XDBL_SMEM * (int)sizeof(float)>>>(xpw, dtw, dtbp, Alogs);
    k_scanB<<<BB*KK*NN, 128>>>(Alogs);
    k_scanC<<<BB*KK*64, 128>>>(Alogs, Ds, dtw, dtbp);
    k_final<<<BB*128, 256>>>(inp, lnw, lnb, Wout, out);
}